// round 10
// baseline (speedup 1.0000x reference)
#include <cuda_runtime.h>
#include <cuda_bf16.h>
#include <math.h>
#include <stdint.h>

// Problem constants
#define Bq   4
#define Lq   1024
#define Dq   1280
#define Hq   20
#define HDq  64
#define BH   (Bq*Hq)     // 80
#define LKV  (2*Lq)      // 2048
#define ALPHA 0.48f
#define Mrows (Bq*Lq)    // 4096

// Scratch (device globals; no allocation allowed)
__device__ float g_Q[BH * Lq * HDq];
__device__ float g_K[BH * LKV * HDq];
__device__ float g_V[BH * LKV * HDq];
__device__ float g_ctx[Bq * Lq * Dq];

// ---------------------------------------------------------------------------
// mma.sync helpers (sm_80+ PTX, valid on compute_100)
// ---------------------------------------------------------------------------
__device__ __forceinline__ uint32_t smem_u32(const void* p) {
    uint32_t a;
    asm("{ .reg .u64 t; cvta.to.shared.u64 t, %1; cvt.u32.u64 %0, t; }"
        : "=r"(a) : "l"(p));
    return a;
}
__device__ __forceinline__ void ldmx4(uint32_t* r, uint32_t addr) {
    asm volatile("ldmatrix.sync.aligned.m8n8.x4.shared.b16 {%0,%1,%2,%3}, [%4];"
                 : "=r"(r[0]), "=r"(r[1]), "=r"(r[2]), "=r"(r[3]) : "r"(addr));
}
__device__ __forceinline__ void ldmx4t(uint32_t* r, uint32_t addr) {
    asm volatile("ldmatrix.sync.aligned.m8n8.x4.trans.shared.b16 {%0,%1,%2,%3}, [%4];"
                 : "=r"(r[0]), "=r"(r[1]), "=r"(r[2]), "=r"(r[3]) : "r"(addr));
}
__device__ __forceinline__ void mma16816(float* c, const uint32_t* a,
                                         const uint32_t b0, const uint32_t b1) {
    asm volatile(
        "mma.sync.aligned.m16n8k16.row.col.f32.bf16.bf16.f32 "
        "{%0,%1,%2,%3}, {%4,%5,%6,%7}, {%8,%9}, {%0,%1,%2,%3};"
        : "+f"(c[0]), "+f"(c[1]), "+f"(c[2]), "+f"(c[3])
        : "r"(a[0]), "r"(a[1]), "r"(a[2]), "r"(a[3]), "r"(b0), "r"(b1));
}

// ---------------------------------------------------------------------------
// bg copy
// ---------------------------------------------------------------------------
__global__ void bg_copy_kernel(const float* __restrict__ Kbg,
                               const float* __restrict__ Vbg)
{
    int i = blockIdx.x * blockDim.x + threadIdx.x;
    const int n = BH * Lq * HDq;
    if (i >= n) return;
    int head = i / (Lq * HDq);
    int rem  = i - head * (Lq * HDq);
    int dst  = head * (LKV * HDq) + (Lq * HDq) + rem;
    g_K[dst] = ALPHA * Kbg[i];
    g_V[dst] = ALPHA * Vbg[i];
}

// ---------------------------------------------------------------------------
// hi/lo split helpers
// ---------------------------------------------------------------------------
__device__ __forceinline__ void cvt_hi_lo(float4 v, uint2& hi, uint2& lo)
{
    uint32_t x0 = __float_as_uint(v.x), x1 = __float_as_uint(v.y);
    uint32_t x2 = __float_as_uint(v.z), x3 = __float_as_uint(v.w);
    hi.x = __byte_perm(x0, x1, 0x7632);
    hi.y = __byte_perm(x2, x3, 0x7632);
    float l0 = v.x - __uint_as_float(x0 & 0xFFFF0000u);
    float l1 = v.y - __uint_as_float(x1 & 0xFFFF0000u);
    float l2 = v.z - __uint_as_float(x2 & 0xFFFF0000u);
    float l3 = v.w - __uint_as_float(x3 & 0xFFFF0000u);
    __nv_bfloat162 lp0 = __floats2bfloat162_rn(l0, l1);
    __nv_bfloat162 lp1 = __floats2bfloat162_rn(l2, l3);
    lo.x = *reinterpret_cast<uint32_t*>(&lp0);
    lo.y = *reinterpret_cast<uint32_t*>(&lp1);
}
__device__ __forceinline__ void pack_hi_lo(float x, float y, uint32_t& hi, uint32_t& lo)
{
    uint32_t xb = __float_as_uint(x), yb = __float_as_uint(y);
    hi = __byte_perm(xb, yb, 0x7632);
    float xl = x - __uint_as_float(xb & 0xFFFF0000u);
    float yl = y - __uint_as_float(yb & 0xFFFF0000u);
    __nv_bfloat162 t = __floats2bfloat162_rn(xl, yl);
    lo = *reinterpret_cast<uint32_t*>(&t);
}

// ---------------------------------------------------------------------------
// Tensor-core GEMM via mma.sync, double-buffered, TERM-MAJOR mma ordering
// (accumulator reuse distance 8 instead of 2).
// C[4096,1280] = A[4096,1280] @ W[1280,1280]
// grid.z selects weight (fused QKV); fused=0 -> single W0 + bias epilogue.
// ---------------------------------------------------------------------------
#define BM 128
#define BN 128
#define BK 32
#define APAD 40
#define BPAD 136
#define A_ELE (BM * APAD)            // 5120
#define B_ELE (BK * BPAD)            // 4352
#define STAGE_ELE (2 * A_ELE + 2 * B_ELE)   // 18944 bf16
#define GEMM_SMEM_BYTES (2 * STAGE_ELE * 2) // 75776

__global__ __launch_bounds__(256)
void gemm_mma_kernel(const float* __restrict__ A,
                     const float* __restrict__ W0,
                     const float* __restrict__ W1,
                     const float* __restrict__ W2,
                     const float* __restrict__ bias,
                     float* __restrict__ C,
                     int fused)
{
    extern __shared__ __align__(16) __nv_bfloat16 smemb[];

    const int tid    = threadIdx.x;
    const int lane   = tid & 31;
    const int wid    = tid >> 5;
    const int warp_m = wid & 3;
    const int warp_n = wid >> 2;
    const int bm     = blockIdx.y * BM;
    const int bn     = blockIdx.x * BN;
    const int wsel   = blockIdx.z;
    const float* W   = (wsel == 0) ? W0 : (wsel == 1 ? W1 : W2);
    const int mode   = fused ? (1 + wsel) : 0;

    const uint32_t smem_base_u = smem_u32(smemb);

    float acc[2][8][4];
#pragma unroll
    for (int i = 0; i < 2; i++)
#pragma unroll
        for (int j = 0; j < 8; j++)
#pragma unroll
            for (int k = 0; k < 4; k++) acc[i][j][k] = 0.f;

    float4 a_pf[4], b_pf[4];
#pragma unroll
    for (int it = 0; it < 4; it++) {
        int i = it * 256 + tid;
        a_pf[it] = *(const float4*)(A + (size_t)(bm + (i >> 3)) * Dq + ((i & 7) << 2));
        b_pf[it] = *(const float4*)(W + (size_t)(i >> 5) * Dq + bn + ((i & 31) << 2));
    }

    // prologue: store chunk 0 into stage 0
    {
        __nv_bfloat16* Ah = smemb;
        __nv_bfloat16* Al = Ah + A_ELE;
        __nv_bfloat16* Bh = Al + A_ELE;
        __nv_bfloat16* Bl = Bh + B_ELE;
#pragma unroll
        for (int it = 0; it < 4; it++) {
            int i  = it * 256 + tid;
            int ar = i >> 3, ac = (i & 7) << 2;
            uint2 hi, lo;
            cvt_hi_lo(a_pf[it], hi, lo);
            *(uint2*)(Ah + ar * APAD + ac) = hi;
            *(uint2*)(Al + ar * APAD + ac) = lo;
            int br = i >> 5, bc = (i & 31) << 2;
            cvt_hi_lo(b_pf[it], hi, lo);
            *(uint2*)(Bh + br * BPAD + bc) = hi;
            *(uint2*)(Bl + br * BPAD + bc) = lo;
        }
    }
    __syncthreads();

    const int NCH = Dq / BK;   // 40
#pragma unroll 1
    for (int c = 0; c < NCH; c++) {
        const int st = c & 1;
        const uint32_t ah_u = smem_base_u + st * (STAGE_ELE * 2);
        const uint32_t al_u = ah_u + A_ELE * 2;
        const uint32_t bh_u = al_u + A_ELE * 2;
        const uint32_t bl_u = bh_u + B_ELE * 2;

        const bool have_next = (c + 1 < NCH);
        if (have_next) {
            int kk = (c + 1) * BK;
#pragma unroll
            for (int it = 0; it < 4; it++) {
                int i = it * 256 + tid;
                a_pf[it] = *(const float4*)(A + (size_t)(bm + (i >> 3)) * Dq + kk + ((i & 7) << 2));
                b_pf[it] = *(const float4*)(W + (size_t)(kk + (i >> 5)) * Dq + bn + ((i & 31) << 2));
            }
        }

        // compute on stage st — term-major ordering over nfp pairs
#pragma unroll
        for (int ks = 0; ks < 2; ks++) {
            uint32_t afh[2][4], afl[2][4];
#pragma unroll
            for (int mf = 0; mf < 2; mf++) {
                int row = warp_m * 32 + mf * 16 + (lane & 7) + ((lane >> 3) & 1) * 8;
                int col = ks * 16 + (lane >> 4) * 8;
                uint32_t off = (uint32_t)(row * APAD + col) * 2;
                ldmx4(afh[mf], ah_u + off);
                ldmx4(afl[mf], al_u + off);
            }
#pragma unroll
            for (int pr = 0; pr < 2; pr++) {
                const int nf0 = pr * 2, nf1 = pr * 2 + 1;
                uint32_t bfh0[4], bfl0[4], bfh1[4], bfl1[4];
                {
                    int krow = ks * 16 + (lane & 7) + ((lane >> 3) & 1) * 8;
                    int nc0  = warp_n * 64 + nf0 * 16 + (lane >> 4) * 8;
                    int nc1  = warp_n * 64 + nf1 * 16 + (lane >> 4) * 8;
                    uint32_t o0 = (uint32_t)(krow * BPAD + nc0) * 2;
                    uint32_t o1 = (uint32_t)(krow * BPAD + nc1) * 2;
                    ldmx4t(bfh0, bh_u + o0);
                    ldmx4t(bfl0, bl_u + o0);
                    ldmx4t(bfh1, bh_u + o1);
                    ldmx4t(bfl1, bl_u + o1);
                }
                // term hh: 8 distinct accumulators
                mma16816(acc[0][nf0 * 2],     afh[0], bfh0[0], bfh0[1]);
                mma16816(acc[0][nf0 * 2 + 1], afh[0], bfh0[2], bfh0[3]);
                mma16816(acc[1][nf0 * 2],     afh[1], bfh0[0], bfh0[1]);
                mma16816(acc[1][nf0 * 2 + 1], afh[1], bfh0[2], bfh0[3]);
                mma16816(acc[0][nf1 * 2],     afh[0], bfh1[0], bfh1[1]);
                mma16816(acc[0][nf1 * 2 + 1], afh[0], bfh1[2], bfh1[3]);
                mma16816(acc[1][nf1 * 2],     afh[1], bfh1[0], bfh1[1]);
                mma16816(acc[1][nf1 * 2 + 1], afh[1], bfh1[2], bfh1[3]);
                // term hl
                mma16816(acc[0][nf0 * 2],     afh[0], bfl0[0], bfl0[1]);
                mma16816(acc[0][nf0 * 2 + 1], afh[0], bfl0[2], bfl0[3]);
                mma16816(acc[1][nf0 * 2],     afh[1], bfl0[0], bfl0[1]);
                mma16816(acc[1][nf0 * 2 + 1], afh[1], bfl0[2], bfl0[3]);
                mma16816(acc[0][nf1 * 2],     afh[0], bfl1[0], bfl1[1]);
                mma16816(acc[0][nf1 * 2 + 1], afh[0], bfl1[2], bfl1[3]);
                mma16816(acc[1][nf1 * 2],     afh[1], bfl1[0], bfl1[1]);
                mma16816(acc[1][nf1 * 2 + 1], afh[1], bfl1[2], bfl1[3]);
                // term lh
                mma16816(acc[0][nf0 * 2],     afl[0], bfh0[0], bfh0[1]);
                mma16816(acc[0][nf0 * 2 + 1], afl[0], bfh0[2], bfh0[3]);
                mma16816(acc[1][nf0 * 2],     afl[1], bfh0[0], bfh0[1]);
                mma16816(acc[1][nf0 * 2 + 1], afl[1], bfh0[2], bfh0[3]);
                mma16816(acc[0][nf1 * 2],     afl[0], bfh1[0], bfh1[1]);
                mma16816(acc[0][nf1 * 2 + 1], afl[0], bfh1[2], bfh1[3]);
                mma16816(acc[1][nf1 * 2],     afl[1], bfh1[0], bfh1[1]);
                mma16816(acc[1][nf1 * 2 + 1], afl[1], bfh1[2], bfh1[3]);
            }
        }

        if (have_next) {
            __nv_bfloat16* base = smemb + (st ^ 1) * STAGE_ELE;
            __nv_bfloat16* Ah = base;
            __nv_bfloat16* Al = Ah + A_ELE;
            __nv_bfloat16* Bh = Al + A_ELE;
            __nv_bfloat16* Bl = Bh + B_ELE;
#pragma unroll
            for (int it = 0; it < 4; it++) {
                int i  = it * 256 + tid;
                int ar = i >> 3, ac = (i & 7) << 2;
                uint2 hi, lo;
                cvt_hi_lo(a_pf[it], hi, lo);
                *(uint2*)(Ah + ar * APAD + ac) = hi;
                *(uint2*)(Al + ar * APAD + ac) = lo;
                int br = i >> 5, bc = (i & 31) << 2;
                cvt_hi_lo(b_pf[it], hi, lo);
                *(uint2*)(Bh + br * BPAD + bc) = hi;
                *(uint2*)(Bl + br * BPAD + bc) = lo;
            }
        }
        __syncthreads();
    }

    // epilogue
    const int group = lane >> 2;
    const int tg    = lane & 3;
#pragma unroll
    for (int mf = 0; mf < 2; mf++) {
#pragma unroll
        for (int nf = 0; nf < 8; nf++) {
            int col = bn + warp_n * 64 + nf * 8 + tg * 2;
#pragma unroll
            for (int half = 0; half < 2; half++) {
                int row = bm + warp_m * 32 + mf * 16 + group + half * 8;
                float v0 = acc[mf][nf][half * 2];
                float v1 = acc[mf][nf][half * 2 + 1];
                if (mode == 0) {
                    v0 += bias[col];
                    v1 += bias[col + 1];
                    *(float2*)(C + (size_t)row * Dq + col) = make_float2(v0, v1);
                } else {
                    int b  = row >> 10;
                    int l  = row & 1023;
                    int h  = col >> 6;
                    int hd = col & 63;
                    float2 v2 = make_float2(v0, v1);
                    if (mode == 1) {
                        *(float2*)(g_Q + (((size_t)(b * Hq + h)) * Lq + l) * HDq + hd) = v2;
                    } else if (mode == 2) {
                        *(float2*)(g_K + (((size_t)(b * Hq + h)) * LKV + l) * HDq + hd) = v2;
                    } else {
                        *(float2*)(g_V + (((size_t)(b * Hq + h)) * LKV + l) * HDq + hd) = v2;
                    }
                }
            }
        }
    }
}

// ---------------------------------------------------------------------------
// Tensor-core flash attention, TERM-MAJOR mma ordering in QK and PV loops.
// Block = 128 queries (8 warps x 16 rows), full 64-dim head per warp.
// Grid = (Lq/128, BH) = (8, 80).
// ---------------------------------------------------------------------------
#define PITCH 72

__global__ __launch_bounds__(256)
void attn_mma_kernel()
{
    __shared__ __align__(16) __nv_bfloat16 sm_t[4 * 64 * PITCH];

    const int head = blockIdx.y;
    const int qb   = blockIdx.x * 128;
    const int tid  = threadIdx.x;
    const int lane = tid & 31;
    const int warp = tid >> 5;

    __nv_bfloat16* Qh_s = sm_t;
    __nv_bfloat16* Ql_s = sm_t + 128 * PITCH;
    __nv_bfloat16* Kh_s = sm_t;
    __nv_bfloat16* Kl_s = sm_t + 64 * PITCH;
    __nv_bfloat16* Vh_s = sm_t + 2 * 64 * PITCH;
    __nv_bfloat16* Vl_s = sm_t + 3 * 64 * PITCH;
    const uint32_t qh_u = smem_u32(Qh_s);
    const uint32_t ql_u = smem_u32(Ql_s);
    const uint32_t kh_u = smem_u32(Kh_s);
    const uint32_t kl_u = smem_u32(Kl_s);
    const uint32_t vh_u = smem_u32(Vh_s);
    const uint32_t vl_u = smem_u32(Vl_s);

    const float* Qp = g_Q + ((size_t)head * Lq + qb) * HDq;
#pragma unroll
    for (int it = 0; it < 8; it++) {
        int i  = it * 256 + tid;
        int r  = i >> 4;
        int c4 = (i & 15) << 2;
        float4 v = *(const float4*)(Qp + r * 64 + c4);
        v.x *= 0.125f; v.y *= 0.125f; v.z *= 0.125f; v.w *= 0.125f;
        uint2 hi, lo;
        cvt_hi_lo(v, hi, lo);
        *(uint2*)(Qh_s + r * PITCH + c4) = hi;
        *(uint2*)(Ql_s + r * PITCH + c4) = lo;
    }
    __syncthreads();

    uint32_t qfh[4][4], qfl[4][4];
    {
        int arow = warp * 16 + (lane & 7) + ((lane >> 3) & 1) * 8;
#pragma unroll
        for (int ks = 0; ks < 4; ks++) {
            uint32_t off = (uint32_t)(arow * PITCH + ks * 16 + (lane >> 4) * 8) * 2;
            ldmx4(qfh[ks], qh_u + off);
            ldmx4(qfl[ks], ql_u + off);
        }
    }
    __syncthreads();

    float O[8][4];
#pragma unroll
    for (int i = 0; i < 8; i++)
#pragma unroll
        for (int j = 0; j < 4; j++) O[i][j] = 0.f;
    float m_r[2] = {-1e30f, -1e30f};
    float l_r[2] = {0.f, 0.f};

    const float* Kp = g_K + (size_t)head * LKV * HDq;
    const float* Vp = g_V + (size_t)head * LKV * HDq;

    float4 kpf[4], vpf[4];
#pragma unroll
    for (int it = 0; it < 4; it++) {
        int i  = it * 256 + tid;
        int r  = i >> 4;
        int c4 = (i & 15) << 2;
        kpf[it] = *(const float4*)(Kp + (size_t)r * 64 + c4);
        vpf[it] = *(const float4*)(Vp + (size_t)r * 64 + c4);
    }

    const int NKT = LKV / 64;   // 32
#pragma unroll 1
    for (int kt = 0; kt < NKT; kt++) {
#pragma unroll
        for (int it = 0; it < 4; it++) {
            int i  = it * 256 + tid;
            int r  = i >> 4;
            int c4 = (i & 15) << 2;
            uint2 hi, lo;
            cvt_hi_lo(kpf[it], hi, lo);
            *(uint2*)(Kh_s + r * PITCH + c4) = hi;
            *(uint2*)(Kl_s + r * PITCH + c4) = lo;
            cvt_hi_lo(vpf[it], hi, lo);
            *(uint2*)(Vh_s + r * PITCH + c4) = hi;
            *(uint2*)(Vl_s + r * PITCH + c4) = lo;
        }
        __syncthreads();

        if (kt + 1 < NKT) {
            const float* kn = Kp + (size_t)(kt + 1) * 64 * 64;
            const float* vn = Vp + (size_t)(kt + 1) * 64 * 64;
#pragma unroll
            for (int it = 0; it < 4; it++) {
                int i  = it * 256 + tid;
                int r  = i >> 4;
                int c4 = (i & 15) << 2;
                kpf[it] = *(const float4*)(kn + (size_t)r * 64 + c4);
                vpf[it] = *(const float4*)(vn + (size_t)r * 64 + c4);
            }
        }

        // ---- S = Q K^T (3-term, term-major over n16 pairs) ----
        float c[8][4];
#pragma unroll
        for (int i = 0; i < 8; i++)
#pragma unroll
            for (int j = 0; j < 4; j++) c[i][j] = 0.f;

#pragma unroll
        for (int ks = 0; ks < 4; ks++) {
#pragma unroll
            for (int pr = 0; pr < 2; pr++) {
                const int n0 = pr * 2, n1 = pr * 2 + 1;
                uint32_t kh0[4], kl0[4], kh1[4], kl1[4];
                {
                    int nrow0 = n0 * 16 + (lane & 7) + (lane >> 4) * 8;
                    int nrow1 = n1 * 16 + (lane & 7) + (lane >> 4) * 8;
                    int kcol  = ks * 16 + ((lane >> 3) & 1) * 8;
                    uint32_t o0 = (uint32_t)(nrow0 * PITCH + kcol) * 2;
                    uint32_t o1 = (uint32_t)(nrow1 * PITCH + kcol) * 2;
                    ldmx4(kh0, kh_u + o0);
                    ldmx4(kl0, kl_u + o0);
                    ldmx4(kh1, kh_u + o1);
                    ldmx4(kl1, kl_u + o1);
                }
                // hh
                mma16816(c[n0 * 2],     qfh[ks], kh0[0], kh0[1]);
                mma16816(c[n0 * 2 + 1], qfh[ks], kh0[2], kh0[3]);
                mma16816(c[n1 * 2],     qfh[ks], kh1[0], kh1[1]);
                mma16816(c[n1 * 2 + 1], qfh[ks], kh1[2], kh1[3]);
                // hl
                mma16816(c[n0 * 2],     qfh[ks], kl0[0], kl0[1]);
                mma16816(c[n0 * 2 + 1], qfh[ks], kl0[2], kl0[3]);
                mma16816(c[n1 * 2],     qfh[ks], kl1[0], kl1[1]);
                mma16816(c[n1 * 2 + 1], qfh[ks], kl1[2], kl1[3]);
                // lh
                mma16816(c[n0 * 2],     qfl[ks], kh0[0], kh0[1]);
                mma16816(c[n0 * 2 + 1], qfl[ks], kh0[2], kh0[3]);
                mma16816(c[n1 * 2],     qfl[ks], kh1[0], kh1[1]);
                mma16816(c[n1 * 2 + 1], qfl[ks], kh1[2], kh1[3]);
            }
        }

        // ---- online softmax in fragment registers ----
#pragma unroll
        for (int h = 0; h < 2; h++) {
            float rm = c[0][2 * h];
#pragma unroll
            for (int nf = 0; nf < 8; nf++) {
                rm = fmaxf(rm, c[nf][2 * h]);
                rm = fmaxf(rm, c[nf][2 * h + 1]);
            }
            rm = fmaxf(rm, __shfl_xor_sync(0xffffffffu, rm, 1));
            rm = fmaxf(rm, __shfl_xor_sync(0xffffffffu, rm, 2));
            float mnew  = fmaxf(m_r[h], rm);
            float alpha = __expf(m_r[h] - mnew);
            float sum = 0.f;
#pragma unroll
            for (int nf = 0; nf < 8; nf++) {
                c[nf][2 * h]     = __expf(c[nf][2 * h] - mnew);
                c[nf][2 * h + 1] = __expf(c[nf][2 * h + 1] - mnew);
                sum += c[nf][2 * h] + c[nf][2 * h + 1];
            }
            sum += __shfl_xor_sync(0xffffffffu, sum, 1);
            sum += __shfl_xor_sync(0xffffffffu, sum, 2);
            l_r[h] = l_r[h] * alpha + sum;
            m_r[h] = mnew;
#pragma unroll
            for (int nf = 0; nf < 8; nf++) {
                O[nf][2 * h]     *= alpha;
                O[nf][2 * h + 1] *= alpha;
            }
        }

        // ---- O += P V (3-term, term-major over nfp pairs) ----
#pragma unroll
        for (int ks = 0; ks < 4; ks++) {
            uint32_t ph[4], pl[4];
            pack_hi_lo(c[2 * ks][0],     c[2 * ks][1],     ph[0], pl[0]);
            pack_hi_lo(c[2 * ks][2],     c[2 * ks][3],     ph[1], pl[1]);
            pack_hi_lo(c[2 * ks + 1][0], c[2 * ks + 1][1], ph[2], pl[2]);
            pack_hi_lo(c[2 * ks + 1][2], c[2 * ks + 1][3], ph[3], pl[3]);
#pragma unroll
            for (int pr = 0; pr < 2; pr++) {
                const int n0 = pr * 2, n1 = pr * 2 + 1;
                uint32_t vh0[4], vl0[4], vh1[4], vl1[4];
                {
                    int krow = ks * 16 + (lane & 7) + ((lane >> 3) & 1) * 8;
                    int nc0  = n0 * 16 + (lane >> 4) * 8;
                    int nc1  = n1 * 16 + (lane >> 4) * 8;
                    uint32_t o0 = (uint32_t)(krow * PITCH + nc0) * 2;
                    uint32_t o1 = (uint32_t)(krow * PITCH + nc1) * 2;
                    ldmx4t(vh0, vh_u + o0);
                    ldmx4t(vl0, vl_u + o0);
                    ldmx4t(vh1, vh_u + o1);
                    ldmx4t(vl1, vl_u + o1);
                }
                // hh
                mma16816(O[n0 * 2],     ph, vh0[0], vh0[1]);
                mma16816(O[n0 * 2 + 1], ph, vh0[2], vh0[3]);
                mma16816(O[n1 * 2],     ph, vh1[0], vh1[1]);
                mma16816(O[n1 * 2 + 1], ph, vh1[2], vh1[3]);
                // hl
                mma16816(O[n0 * 2],     ph, vl0[0], vl0[1]);
                mma16816(O[n0 * 2 + 1], ph, vl0[2], vl0[3]);
                mma16816(O[n1 * 2],     ph, vl1[0], vl1[1]);
                mma16816(O[n1 * 2 + 1], ph, vl1[2], vl1[3]);
                // lh
                mma16816(O[n0 * 2],     pl, vh0[0], vh0[1]);
                mma16816(O[n0 * 2 + 1], pl, vh0[2], vh0[3]);
                mma16816(O[n1 * 2],     pl, vh1[0], vh1[1]);
                mma16816(O[n1 * 2 + 1], pl, vh1[2], vh1[3]);
            }
        }
        __syncthreads();
    }

    const int b = head / Hq;
    const int h = head - b * Hq;
    const int group = lane >> 2;
    const int tg    = lane & 3;
    float inv0 = 1.f / l_r[0];
    float inv1 = 1.f / l_r[1];
    int row0 = qb + warp * 16 + group;
    int row1 = row0 + 8;
#pragma unroll
    for (int nf = 0; nf < 8; nf++) {
        int col = h * HDq + nf * 8 + tg * 2;
        *(float2*)(g_ctx + (size_t)(b * Lq + row0) * Dq + col) =
            make_float2(O[nf][0] * inv0, O[nf][1] * inv0);
        *(float2*)(g_ctx + (size_t)(b * Lq + row1) * Dq + col) =
            make_float2(O[nf][2] * inv1, O[nf][3] * inv1);
    }
}

// ---------------------------------------------------------------------------
// Launch
// ---------------------------------------------------------------------------
extern "C" void kernel_launch(void* const* d_in, const int* in_sizes, int n_in,
                              void* d_out, int out_size)
{
    const float* X   = (const float*)d_in[0];
    const float* Kbg = (const float*)d_in[1];
    const float* Vbg = (const float*)d_in[2];
    const float* Wq  = (const float*)d_in[3];
    const float* Wk  = (const float*)d_in[4];
    const float* Wv  = (const float*)d_in[5];
    const float* Wo  = (const float*)d_in[6];
    const float* bo  = (const float*)d_in[7];
    float* out = (float*)d_out;

    static bool init_done = false;
    static float* ctx_ptr = nullptr;
    if (!init_done) {
        cudaFuncSetAttribute(gemm_mma_kernel,
                             cudaFuncAttributeMaxDynamicSharedMemorySize,
                             GEMM_SMEM_BYTES);
        cudaGetSymbolAddress((void**)&ctx_ptr, g_ctx);
        init_done = true;
    }

    {
        int n = BH * Lq * HDq;
        bg_copy_kernel<<<(n + 255) / 256, 256>>>(Kbg, Vbg);
    }

    // Fused QKV projections: grid.z picks weight + destination
    {
        dim3 qkv_grid(Dq / BN, Mrows / BM, 3);   // (10, 32, 3)
        gemm_mma_kernel<<<qkv_grid, 256, GEMM_SMEM_BYTES>>>(
            X, Wq, Wk, Wv, nullptr, nullptr, 1);
    }

    {
        dim3 agrid(Lq / 128, BH);                // (8, 80)
        attn_mma_kernel<<<agrid, 256>>>();
    }

    // Output projection + bias
    {
        dim3 ogrid(Dq / BN, Mrows / BM, 1);      // (10, 32, 1)
        gemm_mma_kernel<<<ogrid, 256, GEMM_SMEM_BYTES>>>(
            ctx_ptr, Wo, nullptr, nullptr, bo, out, 0);
    }
}

// round 11
// speedup vs baseline: 1.0925x; 1.0925x over previous
#include <cuda_runtime.h>
#include <cuda_bf16.h>
#include <math.h>
#include <stdint.h>

// Problem constants
#define Bq   4
#define Lq   1024
#define Dq   1280
#define Hq   20
#define HDq  64
#define BH   (Bq*Hq)     // 80
#define LKV  (2*Lq)      // 2048
#define ALPHA 0.48f
#define Mrows (Bq*Lq)    // 4096
#define WELEM (Dq*Dq)    // 1,638,400

// Pre-split bf16 scratch (device globals; no allocation allowed)
__device__ __align__(128) __nv_bfloat16 g_Xh[Mrows * Dq];
__device__ __align__(128) __nv_bfloat16 g_Xl[Mrows * Dq];
__device__ __align__(128) __nv_bfloat16 g_Wh[4 * WELEM];
__device__ __align__(128) __nv_bfloat16 g_Wl[4 * WELEM];
__device__ __align__(128) __nv_bfloat16 g_Qh[BH * Lq * HDq];
__device__ __align__(128) __nv_bfloat16 g_Ql[BH * Lq * HDq];
__device__ __align__(128) __nv_bfloat16 g_Kh[BH * LKV * HDq];
__device__ __align__(128) __nv_bfloat16 g_Kl[BH * LKV * HDq];
__device__ __align__(128) __nv_bfloat16 g_Vh[BH * LKV * HDq];
__device__ __align__(128) __nv_bfloat16 g_Vl[BH * LKV * HDq];
__device__ __align__(128) __nv_bfloat16 g_ch[Mrows * Dq];
__device__ __align__(128) __nv_bfloat16 g_cl[Mrows * Dq];

// ---------------------------------------------------------------------------
// PTX helpers
// ---------------------------------------------------------------------------
__device__ __forceinline__ uint32_t smem_u32(const void* p) {
    uint32_t a;
    asm("{ .reg .u64 t; cvta.to.shared.u64 t, %1; cvt.u32.u64 %0, t; }"
        : "=r"(a) : "l"(p));
    return a;
}
__device__ __forceinline__ void ldmx4(uint32_t* r, uint32_t addr) {
    asm volatile("ldmatrix.sync.aligned.m8n8.x4.shared.b16 {%0,%1,%2,%3}, [%4];"
                 : "=r"(r[0]), "=r"(r[1]), "=r"(r[2]), "=r"(r[3]) : "r"(addr));
}
__device__ __forceinline__ void ldmx4t(uint32_t* r, uint32_t addr) {
    asm volatile("ldmatrix.sync.aligned.m8n8.x4.trans.shared.b16 {%0,%1,%2,%3}, [%4];"
                 : "=r"(r[0]), "=r"(r[1]), "=r"(r[2]), "=r"(r[3]) : "r"(addr));
}
__device__ __forceinline__ void mma16816(float* c, const uint32_t* a,
                                         const uint32_t b0, const uint32_t b1) {
    asm volatile(
        "mma.sync.aligned.m16n8k16.row.col.f32.bf16.bf16.f32 "
        "{%0,%1,%2,%3}, {%4,%5,%6,%7}, {%8,%9}, {%0,%1,%2,%3};"
        : "+f"(c[0]), "+f"(c[1]), "+f"(c[2]), "+f"(c[3])
        : "r"(a[0]), "r"(a[1]), "r"(a[2]), "r"(a[3]), "r"(b0), "r"(b1));
}
__device__ __forceinline__ void cpa16(uint32_t d, const void* s) {
    asm volatile("cp.async.cg.shared.global [%0], [%1], 16;" :: "r"(d), "l"(s));
}
#define CP_COMMIT() asm volatile("cp.async.commit_group;" ::: "memory")
#define CP_WAIT1()  asm volatile("cp.async.wait_group 1;" ::: "memory")
#define CP_WAIT0()  asm volatile("cp.async.wait_group 0;" ::: "memory")

// hi/lo split helpers
__device__ __forceinline__ void cvt_hi_lo(float4 v, uint2& hi, uint2& lo)
{
    uint32_t x0 = __float_as_uint(v.x), x1 = __float_as_uint(v.y);
    uint32_t x2 = __float_as_uint(v.z), x3 = __float_as_uint(v.w);
    hi.x = __byte_perm(x0, x1, 0x7632);
    hi.y = __byte_perm(x2, x3, 0x7632);
    float l0 = v.x - __uint_as_float(x0 & 0xFFFF0000u);
    float l1 = v.y - __uint_as_float(x1 & 0xFFFF0000u);
    float l2 = v.z - __uint_as_float(x2 & 0xFFFF0000u);
    float l3 = v.w - __uint_as_float(x3 & 0xFFFF0000u);
    __nv_bfloat162 lp0 = __floats2bfloat162_rn(l0, l1);
    __nv_bfloat162 lp1 = __floats2bfloat162_rn(l2, l3);
    lo.x = *reinterpret_cast<uint32_t*>(&lp0);
    lo.y = *reinterpret_cast<uint32_t*>(&lp1);
}
__device__ __forceinline__ void pack_hi_lo(float x, float y, uint32_t& hi, uint32_t& lo)
{
    uint32_t xb = __float_as_uint(x), yb = __float_as_uint(y);
    hi = __byte_perm(xb, yb, 0x7632);
    float xl = x - __uint_as_float(xb & 0xFFFF0000u);
    float yl = y - __uint_as_float(yb & 0xFFFF0000u);
    __nv_bfloat162 t = __floats2bfloat162_rn(xl, yl);
    lo = *reinterpret_cast<uint32_t*>(&t);
}

// ---------------------------------------------------------------------------
// Prologue: elementwise split kernels
// ---------------------------------------------------------------------------
__global__ void cvt_split_kernel(const float* __restrict__ src,
                                 __nv_bfloat16* __restrict__ dh,
                                 __nv_bfloat16* __restrict__ dl, int n4)
{
    int i = blockIdx.x * blockDim.x + threadIdx.x;
    if (i >= n4) return;
    float4 v = ((const float4*)src)[i];
    uint2 hi, lo;
    cvt_hi_lo(v, hi, lo);
    ((uint2*)dh)[i] = hi;
    ((uint2*)dl)[i] = lo;
}

__global__ void bg_split_kernel(const float* __restrict__ Kbg,
                                const float* __restrict__ Vbg)
{
    int i = blockIdx.x * blockDim.x + threadIdx.x;
    const int n4 = (BH * Lq * HDq) / 4;
    if (i >= n4) return;
    int e    = i * 4;
    int head = e >> 16;           // / (Lq*HDq) = 65536
    int rem  = e & 65535;
    int dst  = head * (LKV * HDq) + (Lq * HDq) + rem;   // multiple of 4
    float4 kv = ((const float4*)Kbg)[i];
    float4 vv = ((const float4*)Vbg)[i];
    kv.x *= ALPHA; kv.y *= ALPHA; kv.z *= ALPHA; kv.w *= ALPHA;
    vv.x *= ALPHA; vv.y *= ALPHA; vv.z *= ALPHA; vv.w *= ALPHA;
    uint2 hi, lo;
    cvt_hi_lo(kv, hi, lo);
    *(uint2*)(g_Kh + dst) = hi;
    *(uint2*)(g_Kl + dst) = lo;
    cvt_hi_lo(vv, hi, lo);
    *(uint2*)(g_Vh + dst) = hi;
    *(uint2*)(g_Vl + dst) = lo;
}

// ---------------------------------------------------------------------------
// Tensor-core GEMM: pre-split bf16 operands, cp.async 2-stage, 2 CTAs/SM.
// C[4096,1280] = A @ W ; grid.z selects weight for fused QKV (widx=z),
// fused=0 -> widx=3 (Wo) + bias fp32 epilogue.
// ---------------------------------------------------------------------------
#define BM 128
#define BN 128
#define BK 32
#define APAD 40
#define BPAD 136
#define A_ELE (BM * APAD)            // 5120
#define B_ELE (BK * BPAD)            // 4352
#define STAGE_ELE (2 * A_ELE + 2 * B_ELE)   // 18944 elems
#define GEMM_SMEM_BYTES (2 * STAGE_ELE * 2) // 75776

__global__ __launch_bounds__(256, 2)
void gemm_mma_kernel(const __nv_bfloat16* __restrict__ Ah_g,
                     const __nv_bfloat16* __restrict__ Al_g,
                     const float* __restrict__ bias,
                     float* __restrict__ C,
                     int fused)
{
    extern __shared__ __align__(16) __nv_bfloat16 smemb[];

    const int tid    = threadIdx.x;
    const int lane   = tid & 31;
    const int wid    = tid >> 5;
    const int warp_m = wid & 3;
    const int warp_n = wid >> 2;
    const int bm     = blockIdx.y * BM;
    const int bn     = blockIdx.x * BN;
    const int widx   = fused ? (int)blockIdx.z : 3;
    const int mode   = fused ? (1 + (int)blockIdx.z) : 0;
    const __nv_bfloat16* Wh_g = g_Wh + (size_t)widx * WELEM;
    const __nv_bfloat16* Wl_g = g_Wl + (size_t)widx * WELEM;

    const uint32_t smem_base_u = smem_u32(smemb);

    float acc[2][8][4];
#pragma unroll
    for (int i = 0; i < 2; i++)
#pragma unroll
        for (int j = 0; j < 8; j++)
#pragma unroll
            for (int k = 0; k < 4; k++) acc[i][j][k] = 0.f;

    // fill helper (8 cp.async per thread per stage)
    auto fill = [&](int st, int kk) {
        uint32_t ah = smem_base_u + (st * STAGE_ELE) * 2;
        uint32_t al = ah + A_ELE * 2;
        uint32_t bh = al + A_ELE * 2;
        uint32_t bl = bh + B_ELE * 2;
#pragma unroll
        for (int rep = 0; rep < 2; rep++) {
            int q  = rep * 256 + tid;         // 0..511
            int ar = q >> 2, aj = q & 3;      // A: 4 chunks/row
            uint32_t aoff = (uint32_t)(ar * APAD + aj * 8) * 2;
            const __nv_bfloat16* asrc = Ah_g + (size_t)(bm + ar) * Dq + kk + aj * 8;
            cpa16(ah + aoff, asrc);
            cpa16(al + aoff, Al_g + (size_t)(bm + ar) * Dq + kk + aj * 8);
            int br = q >> 4, bj = q & 15;     // B: 16 chunks/row
            uint32_t boff = (uint32_t)(br * BPAD + bj * 8) * 2;
            cpa16(bh + boff, Wh_g + (size_t)(kk + br) * Dq + bn + bj * 8);
            cpa16(bl + boff, Wl_g + (size_t)(kk + br) * Dq + bn + bj * 8);
        }
    };

    fill(0, 0);
    CP_COMMIT();

    const int NCH = Dq / BK;   // 40
#pragma unroll 1
    for (int c = 0; c < NCH; c++) {
        const int st = c & 1;
        if (c + 1 < NCH) {
            fill(st ^ 1, (c + 1) * BK);
            CP_COMMIT();
            CP_WAIT1();
        } else {
            CP_WAIT0();
        }
        __syncthreads();

        const uint32_t ah_u = smem_base_u + (st * STAGE_ELE) * 2;
        const uint32_t al_u = ah_u + A_ELE * 2;
        const uint32_t bh_u = al_u + A_ELE * 2;
        const uint32_t bl_u = bh_u + B_ELE * 2;

#pragma unroll
        for (int ks = 0; ks < 2; ks++) {
            uint32_t afh[2][4], afl[2][4];
#pragma unroll
            for (int mf = 0; mf < 2; mf++) {
                int row = warp_m * 32 + mf * 16 + (lane & 7) + ((lane >> 3) & 1) * 8;
                int col = ks * 16 + (lane >> 4) * 8;
                uint32_t off = (uint32_t)(row * APAD + col) * 2;
                ldmx4(afh[mf], ah_u + off);
                ldmx4(afl[mf], al_u + off);
            }
#pragma unroll
            for (int nfp = 0; nfp < 4; nfp++) {
                int krow = ks * 16 + (lane & 7) + ((lane >> 3) & 1) * 8;
                int ncol = warp_n * 64 + nfp * 16 + (lane >> 4) * 8;
                uint32_t off = (uint32_t)(krow * BPAD + ncol) * 2;
                uint32_t bfh[4], bfl[4];
                ldmx4t(bfh, bh_u + off);
                ldmx4t(bfl, bl_u + off);
#pragma unroll
                for (int mf = 0; mf < 2; mf++) {
                    float* c0 = acc[mf][nfp * 2];
                    float* c1 = acc[mf][nfp * 2 + 1];
                    mma16816(c0, afh[mf], bfh[0], bfh[1]);
                    mma16816(c1, afh[mf], bfh[2], bfh[3]);
                    mma16816(c0, afh[mf], bfl[0], bfl[1]);
                    mma16816(c1, afh[mf], bfl[2], bfl[3]);
                    mma16816(c0, afl[mf], bfh[0], bfh[1]);
                    mma16816(c1, afl[mf], bfh[2], bfh[3]);
                }
            }
        }
        __syncthreads();
    }

    // epilogue
    const int group = lane >> 2;
    const int tg    = lane & 3;
#pragma unroll
    for (int mf = 0; mf < 2; mf++) {
#pragma unroll
        for (int nf = 0; nf < 8; nf++) {
            int col = bn + warp_n * 64 + nf * 8 + tg * 2;
#pragma unroll
            for (int half = 0; half < 2; half++) {
                int row = bm + warp_m * 32 + mf * 16 + group + half * 8;
                float v0 = acc[mf][nf][half * 2];
                float v1 = acc[mf][nf][half * 2 + 1];
                if (mode == 0) {
                    v0 += bias[col];
                    v1 += bias[col + 1];
                    *(float2*)(C + (size_t)row * Dq + col) = make_float2(v0, v1);
                } else {
                    int b  = row >> 10;
                    int l  = row & 1023;
                    int h  = col >> 6;
                    int hd = col & 63;
                    uint32_t hi, lo;
                    if (mode == 1) {
                        // Q: pre-scale by 1/sqrt(64)
                        pack_hi_lo(v0 * 0.125f, v1 * 0.125f, hi, lo);
                        size_t idx = (((size_t)(b * Hq + h)) * Lq + l) * HDq + hd;
                        *(uint32_t*)(g_Qh + idx) = hi;
                        *(uint32_t*)(g_Ql + idx) = lo;
                    } else {
                        pack_hi_lo(v0, v1, hi, lo);
                        size_t idx = (((size_t)(b * Hq + h)) * LKV + l) * HDq + hd;
                        if (mode == 2) {
                            *(uint32_t*)(g_Kh + idx) = hi;
                            *(uint32_t*)(g_Kl + idx) = lo;
                        } else {
                            *(uint32_t*)(g_Vh + idx) = hi;
                            *(uint32_t*)(g_Vl + idx) = lo;
                        }
                    }
                }
            }
        }
    }
}

// ---------------------------------------------------------------------------
// Tensor-core flash attention: pre-split bf16 Q/K/V, cp.async 2-stage K/V,
// dedicated Q smem region (fragments reloaded per ks), 2 CTAs/SM target.
// Block = 128 queries (8 warps x 16 rows); grid = (8, 80).
// ---------------------------------------------------------------------------
#define PITCH 72
#define QSZ   (128 * PITCH)          // 9216 elems per Q array
#define KARR  (64 * PITCH)           // 4608 elems per K/V array
#define ASTG  (4 * KARR)             // 18432 elems per stage
#define ATTN_SMEM_BYTES ((2 * QSZ + 2 * ASTG) * 2)   // 110592

__global__ __launch_bounds__(256, 2)
void attn_mma_kernel()
{
    extern __shared__ __align__(16) __nv_bfloat16 smemb[];

    const int head = blockIdx.y;
    const int qb   = blockIdx.x * 128;
    const int tid  = threadIdx.x;
    const int lane = tid & 31;
    const int warp = tid >> 5;

    const uint32_t base_u = smem_u32(smemb);
    const uint32_t qh_u = base_u;
    const uint32_t ql_u = qh_u + QSZ * 2;

    // ---- Prologue: load pre-split Q tile (uint4 = 8 bf16) ----
    {
        const __nv_bfloat16* Qh_g = g_Qh + ((size_t)head * Lq + qb) * HDq;
        const __nv_bfloat16* Ql_g = g_Ql + ((size_t)head * Lq + qb) * HDq;
#pragma unroll
        for (int it = 0; it < 4; it++) {
            int q  = it * 256 + tid;    // 0..1023 chunks (128 rows x 8)
            int r  = q >> 3;
            int j  = q & 7;
            uint4 vh = *(const uint4*)(Qh_g + (size_t)r * HDq + j * 8);
            uint4 vl = *(const uint4*)(Ql_g + (size_t)r * HDq + j * 8);
            *(uint4*)(smemb + r * PITCH + j * 8) = vh;
            *(uint4*)(smemb + QSZ + r * PITCH + j * 8) = vl;
        }
    }

    const __nv_bfloat16* Kh_g = g_Kh + (size_t)head * LKV * HDq;
    const __nv_bfloat16* Kl_g = g_Kl + (size_t)head * LKV * HDq;
    const __nv_bfloat16* Vh_g = g_Vh + (size_t)head * LKV * HDq;
    const __nv_bfloat16* Vl_g = g_Vl + (size_t)head * LKV * HDq;

    auto fill = [&](int st, int kt) {
        uint32_t sb = base_u + (2 * QSZ + st * ASTG) * 2;
        size_t gb = (size_t)(kt * 64) * HDq;
#pragma unroll
        for (int rep = 0; rep < 2; rep++) {
            int q = rep * 256 + tid;      // 0..511 (64 rows x 8 chunks)
            int r = q >> 3, j = q & 7;
            uint32_t soff = (uint32_t)(r * PITCH + j * 8) * 2;
            size_t goff = gb + (size_t)r * HDq + j * 8;
            cpa16(sb + 0 * KARR * 2 + soff, Kh_g + goff);
            cpa16(sb + 1 * KARR * 2 + soff, Kl_g + goff);
            cpa16(sb + 2 * KARR * 2 + soff, Vh_g + goff);
            cpa16(sb + 3 * KARR * 2 + soff, Vl_g + goff);
        }
    };

    fill(0, 0);
    CP_COMMIT();
    __syncthreads();   // Q smem ready for all threads

    float O[8][4];
#pragma unroll
    for (int i = 0; i < 8; i++)
#pragma unroll
        for (int j = 0; j < 4; j++) O[i][j] = 0.f;
    float m_r[2] = {-1e30f, -1e30f};
    float l_r[2] = {0.f, 0.f};

    const int NKT = LKV / 64;   // 32
#pragma unroll 1
    for (int kt = 0; kt < NKT; kt++) {
        const int st = kt & 1;
        if (kt + 1 < NKT) {
            fill(st ^ 1, kt + 1);
            CP_COMMIT();
            CP_WAIT1();
        } else {
            CP_WAIT0();
        }
        __syncthreads();

        const uint32_t kh_u = base_u + (2 * QSZ + st * ASTG) * 2;
        const uint32_t kl_u = kh_u + KARR * 2;
        const uint32_t vh_u = kl_u + KARR * 2;
        const uint32_t vl_u = vh_u + KARR * 2;

        // ---- S = Q K^T (3-term) ----
        float c[8][4];
#pragma unroll
        for (int i = 0; i < 8; i++)
#pragma unroll
            for (int j = 0; j < 4; j++) c[i][j] = 0.f;

#pragma unroll
        for (int ks = 0; ks < 4; ks++) {
            uint32_t qfh[4], qfl[4];
            {
                int arow = warp * 16 + (lane & 7) + ((lane >> 3) & 1) * 8;
                uint32_t qoff = (uint32_t)(arow * PITCH + ks * 16 + (lane >> 4) * 8) * 2;
                ldmx4(qfh, qh_u + qoff);
                ldmx4(qfl, ql_u + qoff);
            }
#pragma unroll
            for (int n16 = 0; n16 < 4; n16++) {
                int nrow = n16 * 16 + (lane & 7) + (lane >> 4) * 8;
                int kcol = ks * 16 + ((lane >> 3) & 1) * 8;
                uint32_t off = (uint32_t)(nrow * PITCH + kcol) * 2;
                uint32_t kh[4], kl[4];
                ldmx4(kh, kh_u + off);
                ldmx4(kl, kl_u + off);
                float* c0 = c[n16 * 2];
                float* c1 = c[n16 * 2 + 1];
                mma16816(c0, qfh, kh[0], kh[1]);
                mma16816(c1, qfh, kh[2], kh[3]);
                mma16816(c0, qfh, kl[0], kl[1]);
                mma16816(c1, qfh, kl[2], kl[3]);
                mma16816(c0, qfl, kh[0], kh[1]);
                mma16816(c1, qfl, kh[2], kh[3]);
            }
        }

        // ---- online softmax in fragment registers ----
#pragma unroll
        for (int h = 0; h < 2; h++) {
            float rm = c[0][2 * h];
#pragma unroll
            for (int nf = 0; nf < 8; nf++) {
                rm = fmaxf(rm, c[nf][2 * h]);
                rm = fmaxf(rm, c[nf][2 * h + 1]);
            }
            rm = fmaxf(rm, __shfl_xor_sync(0xffffffffu, rm, 1));
            rm = fmaxf(rm, __shfl_xor_sync(0xffffffffu, rm, 2));
            float mnew  = fmaxf(m_r[h], rm);
            float alpha = __expf(m_r[h] - mnew);
            float sum = 0.f;
#pragma unroll
            for (int nf = 0; nf < 8; nf++) {
                c[nf][2 * h]     = __expf(c[nf][2 * h] - mnew);
                c[nf][2 * h + 1] = __expf(c[nf][2 * h + 1] - mnew);
                sum += c[nf][2 * h] + c[nf][2 * h + 1];
            }
            sum += __shfl_xor_sync(0xffffffffu, sum, 1);
            sum += __shfl_xor_sync(0xffffffffu, sum, 2);
            l_r[h] = l_r[h] * alpha + sum;
            m_r[h] = mnew;
#pragma unroll
            for (int nf = 0; nf < 8; nf++) {
                O[nf][2 * h]     *= alpha;
                O[nf][2 * h + 1] *= alpha;
            }
        }

        // ---- O += P V (3-term) ----
#pragma unroll
        for (int ks = 0; ks < 4; ks++) {
            uint32_t ph[4], pl[4];
            pack_hi_lo(c[2 * ks][0],     c[2 * ks][1],     ph[0], pl[0]);
            pack_hi_lo(c[2 * ks][2],     c[2 * ks][3],     ph[1], pl[1]);
            pack_hi_lo(c[2 * ks + 1][0], c[2 * ks + 1][1], ph[2], pl[2]);
            pack_hi_lo(c[2 * ks + 1][2], c[2 * ks + 1][3], ph[3], pl[3]);
#pragma unroll
            for (int nfp = 0; nfp < 4; nfp++) {
                int krow = ks * 16 + (lane & 7) + ((lane >> 3) & 1) * 8;
                int ncol = nfp * 16 + (lane >> 4) * 8;
                uint32_t off = (uint32_t)(krow * PITCH + ncol) * 2;
                uint32_t vh[4], vl[4];
                ldmx4t(vh, vh_u + off);
                ldmx4t(vl, vl_u + off);
                float* o0 = O[nfp * 2];
                float* o1 = O[nfp * 2 + 1];
                mma16816(o0, ph, vh[0], vh[1]);
                mma16816(o1, ph, vh[2], vh[3]);
                mma16816(o0, ph, vl[0], vl[1]);
                mma16816(o1, ph, vl[2], vl[3]);
                mma16816(o0, pl, vh[0], vh[1]);
                mma16816(o1, pl, vh[2], vh[3]);
            }
        }
        __syncthreads();
    }

    // ---- epilogue: write ctx pre-split (bf16 hi/lo) ----
    const int b = head / Hq;
    const int h = head - b * Hq;
    const int group = lane >> 2;
    const int tg    = lane & 3;
    float inv0 = 1.f / l_r[0];
    float inv1 = 1.f / l_r[1];
    int row0 = qb + warp * 16 + group;
    int row1 = row0 + 8;
#pragma unroll
    for (int nf = 0; nf < 8; nf++) {
        int col = h * HDq + nf * 8 + tg * 2;
        uint32_t hi, lo;
        size_t i0 = (size_t)(b * Lq + row0) * Dq + col;
        size_t i1 = (size_t)(b * Lq + row1) * Dq + col;
        pack_hi_lo(O[nf][0] * inv0, O[nf][1] * inv0, hi, lo);
        *(uint32_t*)(g_ch + i0) = hi;
        *(uint32_t*)(g_cl + i0) = lo;
        pack_hi_lo(O[nf][2] * inv1, O[nf][3] * inv1, hi, lo);
        *(uint32_t*)(g_ch + i1) = hi;
        *(uint32_t*)(g_cl + i1) = lo;
    }
}

// ---------------------------------------------------------------------------
// Launch
// ---------------------------------------------------------------------------
extern "C" void kernel_launch(void* const* d_in, const int* in_sizes, int n_in,
                              void* d_out, int out_size)
{
    const float* X   = (const float*)d_in[0];
    const float* Kbg = (const float*)d_in[1];
    const float* Vbg = (const float*)d_in[2];
    const float* Wq  = (const float*)d_in[3];
    const float* Wk  = (const float*)d_in[4];
    const float* Wv  = (const float*)d_in[5];
    const float* Wo  = (const float*)d_in[6];
    const float* bo  = (const float*)d_in[7];
    float* out = (float*)d_out;

    static bool init_done = false;
    static __nv_bfloat16 *xh, *xl, *wh, *wl, *ch, *cl;
    if (!init_done) {
        cudaFuncSetAttribute(gemm_mma_kernel,
                             cudaFuncAttributeMaxDynamicSharedMemorySize,
                             GEMM_SMEM_BYTES);
        cudaFuncSetAttribute(attn_mma_kernel,
                             cudaFuncAttributeMaxDynamicSharedMemorySize,
                             ATTN_SMEM_BYTES);
        cudaGetSymbolAddress((void**)&xh, g_Xh);
        cudaGetSymbolAddress((void**)&xl, g_Xl);
        cudaGetSymbolAddress((void**)&wh, g_Wh);
        cudaGetSymbolAddress((void**)&wl, g_Wl);
        cudaGetSymbolAddress((void**)&ch, g_ch);
        cudaGetSymbolAddress((void**)&cl, g_cl);
        init_done = true;
    }

    // Prologue: split everything once
    {
        int n4x = (Mrows * Dq) / 4;        // 1,310,720
        cvt_split_kernel<<<(n4x + 255) / 256, 256>>>(X, xh, xl, n4x);
        int n4w = WELEM / 4;               // 409,600
        cvt_split_kernel<<<(n4w + 255) / 256, 256>>>(Wq, wh, wl, n4w);
        cvt_split_kernel<<<(n4w + 255) / 256, 256>>>(Wk, wh + WELEM, wl + WELEM, n4w);
        cvt_split_kernel<<<(n4w + 255) / 256, 256>>>(Wv, wh + 2 * WELEM, wl + 2 * WELEM, n4w);
        cvt_split_kernel<<<(n4w + 255) / 256, 256>>>(Wo, wh + 3 * WELEM, wl + 3 * WELEM, n4w);
        int n4b = (BH * Lq * HDq) / 4;
        bg_split_kernel<<<(n4b + 255) / 256, 256>>>(Kbg, Vbg);
    }

    // Fused QKV projections
    {
        dim3 qkv_grid(Dq / BN, Mrows / BM, 3);   // (10, 32, 3)
        gemm_mma_kernel<<<qkv_grid, 256, GEMM_SMEM_BYTES>>>(
            xh, xl, nullptr, nullptr, 1);
    }

    // Attention
    {
        dim3 agrid(Lq / 128, BH);                // (8, 80)
        attn_mma_kernel<<<agrid, 256, ATTN_SMEM_BYTES>>>();
    }

    // Output projection + bias
    {
        dim3 ogrid(Dq / BN, Mrows / BM, 1);
        gemm_mma_kernel<<<ogrid, 256, GEMM_SMEM_BYTES>>>(
            ch, cl, bo, out, 0);
    }
}